// round 16
// baseline (speedup 1.0000x reference)
#include <cuda_runtime.h>
#include <cuda_fp16.h>
#include <cstdint>

#define N_USERS 200000
#define N_ITEMS 400000
#define N_NODES 600000
#define EMB_DIM 128
#define N_EDGES 3000000
#define VEC4_PER_ROW 32
#define TOTAL_F ((size_t)N_NODES * EMB_DIM)
#define TOTAL_V4 (TOTAL_F / 4)

#define SCAN_BLOCK 1024
#define N_SCAN_BLOCKS ((N_NODES + SCAN_BLOCK - 1) / SCAN_BLOCK)  // 586
#define DEG_BINS 33   // degree 0..31, 32 = "32+"

// Static scratch (allowed: __device__ globals; zero-init on load)
__device__ __align__(256) __half g_bufX[TOTAL_F];
__device__ __align__(256) __half g_bufA[TOTAL_F];
__device__ __align__(256) __half g_bufB[TOTAL_F];
__device__ int  g_count[N_NODES];    // re-zeroed every replay by rowsort
__device__ int  g_offsetL[N_NODES];
__device__ int  g_pos[N_NODES];
__device__ int  g_bsum[SCAN_BLOCK];
__device__ int  g_degHist[DEG_BINS]; // zeroed every replay by hist_convert
__device__ int  g_degPos[DEG_BINS];  // seeded every replay by scan2
__device__ int  g_rowOrder[N_NODES]; // rows sorted by degree
__device__ int2 g_pair[N_EDGES];

// ---------------------------------------------------------------------------
// Launch 1: histogram (4 edges/thread) + fp32->fp16 conversion + degHist reset
// ---------------------------------------------------------------------------
__global__ void hist_convert_kernel(const int4* __restrict__ rows4,
                                    int* __restrict__ count,
                                    const float4* __restrict__ user,
                                    const float4* __restrict__ item,
                                    uint2* __restrict__ X2) {
    size_t tid = (size_t)blockIdx.x * blockDim.x + threadIdx.x;
    if (tid < DEG_BINS) g_degHist[tid] = 0;
    if (tid < N_EDGES / 4) {
        int4 r4 = __ldcs(rows4 + tid);
        atomicAdd(&count[r4.x], 1);
        atomicAdd(&count[r4.y], 1);
        atomicAdd(&count[r4.z], 1);
        atomicAdd(&count[r4.w], 1);
    }
    const size_t user_v4 = (size_t)N_USERS * VEC4_PER_ROW;
    size_t stride = (size_t)gridDim.x * blockDim.x;
    for (size_t i = tid; i < TOTAL_V4; i += stride) {
        float4 v = (i < user_v4) ? __ldcs(user + i) : __ldcs(item + i - user_v4);
        __half2 h0 = __floats2half2_rn(v.x, v.y);
        __half2 h1 = __floats2half2_rn(v.z, v.w);
        uint2 raw;
        raw.x = *reinterpret_cast<unsigned*>(&h0);
        raw.y = *reinterpret_cast<unsigned*>(&h1);
        __stcs(X2 + i, raw);
    }
}

// ---------------------------------------------------------------------------
// Launch 2: block-local exclusive scan + per-block degree histogram.
// (count is NOT zeroed here anymore; rowsort does it.)
// ---------------------------------------------------------------------------
__global__ void scan1_kernel(const int* __restrict__ count,
                             int* __restrict__ offsetL,
                             int* __restrict__ pos,
                             int* __restrict__ bsum) {
    __shared__ int sh[SCAN_BLOCK];
    __shared__ int dh[DEG_BINS];
    int i = blockIdx.x * SCAN_BLOCK + threadIdx.x;
    if (threadIdx.x < DEG_BINS) dh[threadIdx.x] = 0;
    int v = (i < N_NODES) ? count[i] : 0;
    sh[threadIdx.x] = v;
    __syncthreads();
    if (i < N_NODES) atomicAdd(&dh[v < 32 ? v : 32], 1);
    #pragma unroll
    for (int d = 1; d < SCAN_BLOCK; d <<= 1) {
        int t = (threadIdx.x >= d) ? sh[threadIdx.x - d] : 0;
        __syncthreads();
        sh[threadIdx.x] += t;
        __syncthreads();
    }
    if (i < N_NODES) {
        int excl = sh[threadIdx.x] - v;
        offsetL[i] = excl;
        pos[i] = excl;
    }
    if (threadIdx.x == SCAN_BLOCK - 1) bsum[blockIdx.x] = sh[SCAN_BLOCK - 1];
    __syncthreads();
    if (threadIdx.x < DEG_BINS) atomicAdd(&g_degHist[threadIdx.x], dh[threadIdx.x]);
}

// ---------------------------------------------------------------------------
// Launch 3: scan of block sums + exclusive scan of the 33-bin degree histogram
// ---------------------------------------------------------------------------
__global__ void scan2_kernel(int* __restrict__ bsum, int nb) {
    __shared__ int sh[SCAN_BLOCK];
    int v = (threadIdx.x < nb) ? bsum[threadIdx.x] : 0;
    sh[threadIdx.x] = v;
    __syncthreads();
    #pragma unroll
    for (int d = 1; d < SCAN_BLOCK; d <<= 1) {
        int t = (threadIdx.x >= d) ? sh[threadIdx.x - d] : 0;
        __syncthreads();
        sh[threadIdx.x] += t;
        __syncthreads();
    }
    if (threadIdx.x < nb) bsum[threadIdx.x] = sh[threadIdx.x] - v;  // exclusive
    if (threadIdx.x == 0) {
        int run = 0;
        #pragma unroll
        for (int d = 0; d < DEG_BINS; ++d) {
            int c = g_degHist[d];
            g_degPos[d] = run;
            run += c;
        }
    }
}

// ---------------------------------------------------------------------------
// Launch 4: counting-sort rows by degree; restore count=0 replay invariant
// ---------------------------------------------------------------------------
__global__ void rowsort_kernel(int* __restrict__ count,
                               int* __restrict__ rowOrder) {
    int i = blockIdx.x * blockDim.x + threadIdx.x;
    if (i >= N_NODES) return;
    int d = count[i];
    count[i] = 0;                       // replay invariant
    if (d > 32) d = 32;
    int slot = atomicAdd(&g_degPos[d], 1);
    rowOrder[slot] = i;
}

// ---------------------------------------------------------------------------
// Launch 5: permute (4 edges/thread)
// ---------------------------------------------------------------------------
__global__ void permute_kernel(const int4* __restrict__ rows4,
                               const int4* __restrict__ cols4,
                               const float4* __restrict__ vals4,
                               int* __restrict__ pos,
                               const int* __restrict__ bsum,
                               int2* __restrict__ pair) {
    int t = blockIdx.x * blockDim.x + threadIdx.x;
    if (t >= N_EDGES / 4) return;
    int4 r4 = __ldcs(rows4 + t);
    int4 c4 = __ldcs(cols4 + t);
    float4 v4 = __ldcs(vals4 + t);

    int p0 = atomicAdd(&pos[r4.x], 1) + __ldg(&bsum[r4.x >> 10]);
    int p1 = atomicAdd(&pos[r4.y], 1) + __ldg(&bsum[r4.y >> 10]);
    int p2 = atomicAdd(&pos[r4.z], 1) + __ldg(&bsum[r4.z >> 10]);
    int p3 = atomicAdd(&pos[r4.w], 1) + __ldg(&bsum[r4.w >> 10]);

    int2 e;
    e.x = c4.x; e.y = __float_as_int(v4.x); __stcs(pair + p0, e);
    e.x = c4.y; e.y = __float_as_int(v4.y); __stcs(pair + p1, e);
    e.x = c4.z; e.y = __float_as_int(v4.z); __stcs(pair + p2, e);
    e.x = c4.w; e.y = __float_as_int(v4.w); __stcs(pair + p3, e);
}

// ---------------------------------------------------------------------------
// Gather (exact R9 form): LDG.256 + L2 evict_last, FMA into 16 fp32 accs
// ---------------------------------------------------------------------------
__device__ __forceinline__ void gather_acc(const __half* __restrict__ srcH,
                                           int col, int sub, float v,
                                           float* acc) {
    const char* p = reinterpret_cast<const char*>(srcH)
                    + ((size_t)col << 8) + (sub << 5);
    uint32_t q0, q1, q2, q3, q4, q5, q6, q7;
    asm volatile(
        "ld.global.nc.L2::evict_last.v8.b32 {%0,%1,%2,%3,%4,%5,%6,%7}, [%8];"
        : "=r"(q0), "=r"(q1), "=r"(q2), "=r"(q3),
          "=r"(q4), "=r"(q5), "=r"(q6), "=r"(q7)
        : "l"(p));
    uint32_t q[8] = {q0, q1, q2, q3, q4, q5, q6, q7};
    #pragma unroll
    for (int i = 0; i < 8; ++i) {
        __half2 h = *reinterpret_cast<__half2*>(&q[i]);
        float2 f = __half22float2(h);
        acc[2 * i]     += v * f.x;
        acc[2 * i + 1] += v * f.y;
    }
}

__device__ __forceinline__ void unpack16(uint4 lo, uint4 hi, float* f) {
    uint32_t q[8] = {lo.x, lo.y, lo.z, lo.w, hi.x, hi.y, hi.z, hi.w};
    #pragma unroll
    for (int i = 0; i < 8; ++i) {
        __half2 h = *reinterpret_cast<__half2*>(&q[i]);
        float2 t = __half22float2(h);
        f[2 * i] = t.x;
        f[2 * i + 1] = t.y;
    }
}

// ---------------------------------------------------------------------------
// Launches 6-8: pull SpMM, EXACT R9 body, but rows assigned via rowOrder so
// every block holds near-equal-degree rows (block retirement = mean, not max).
// ---------------------------------------------------------------------------
template <bool FUSED>
__global__ void __launch_bounds__(256)
spmm_kernel(const int* __restrict__ offsetL,
            const int* __restrict__ bsum,
            const int* __restrict__ rowOrder,
            const int2* __restrict__ pair,
            const __half* __restrict__ xH,
            __half* __restrict__ dstH,
            const float4* __restrict__ u,
            const float4* __restrict__ it,
            const __half* __restrict__ accA,
            const __half* __restrict__ accB,
            float4* __restrict__ out) {
    int sub = threadIdx.x & 7;
    int gid = (blockIdx.x * blockDim.x + threadIdx.x) >> 3;
    if (gid >= N_NODES) return;
    int r = __ldg(rowOrder + gid);   // degree-sorted assignment (broadcast)

    int j = __ldg(offsetL + r) + __ldg(bsum + (r >> 10));
    int end = (r == N_NODES - 1)
                  ? N_EDGES
                  : __ldg(offsetL + r + 1) + __ldg(bsum + ((r + 1) >> 10));

    float acc[16];
    #pragma unroll
    for (int k = 0; k < 16; ++k) acc[k] = 0.f;

    #pragma unroll 1
    for (; j + 2 <= end; j += 2) {
        int2 e0 = __ldcs(pair + j);
        int2 e1 = __ldcs(pair + j + 1);
        gather_acc(xH, e0.x, sub, __int_as_float(e0.y), acc);
        gather_acc(xH, e1.x, sub, __int_as_float(e1.y), acc);
    }
    if (j < end) {
        int2 e0 = __ldcs(pair + j);
        gather_acc(xH, e0.x, sub, __int_as_float(e0.y), acc);
    }

    if (FUSED) {
        const uint4* aRow = reinterpret_cast<const uint4*>(accA + (size_t)r * EMB_DIM);
        const uint4* bRow = reinterpret_cast<const uint4*>(accB + (size_t)r * EMB_DIM);
        float a[16], b[16];
        unpack16(__ldcs(aRow + 2 * sub), __ldcs(aRow + 2 * sub + 1), a);
        unpack16(__ldcs(bRow + 2 * sub), __ldcs(bRow + 2 * sub + 1), b);

        const float4* xr = (r < N_USERS)
                               ? (u + (size_t)r * VEC4_PER_ROW)
                               : (it + (size_t)(r - N_USERS) * VEC4_PER_ROW);
        float4* orow = out + (size_t)r * VEC4_PER_ROW + 4 * sub;
        #pragma unroll
        for (int q = 0; q < 4; ++q) {
            float4 x0 = __ldcs(xr + 4 * sub + q);
            float4 o;
            o.x = 0.25f * (x0.x + a[4 * q + 0] + b[4 * q + 0] + acc[4 * q + 0]);
            o.y = 0.25f * (x0.y + a[4 * q + 1] + b[4 * q + 1] + acc[4 * q + 1]);
            o.z = 0.25f * (x0.z + a[4 * q + 2] + b[4 * q + 2] + acc[4 * q + 2]);
            o.w = 0.25f * (x0.w + a[4 * q + 3] + b[4 * q + 3] + acc[4 * q + 3]);
            __stcs(orow + q, o);
        }
    } else {
        uint32_t q[8];
        #pragma unroll
        for (int i = 0; i < 8; ++i) {
            __half2 h = __floats2half2_rn(acc[2 * i], acc[2 * i + 1]);
            q[i] = *reinterpret_cast<unsigned*>(&h);
        }
        uint4* drow = reinterpret_cast<uint4*>(dstH + (size_t)r * EMB_DIM) + 2 * sub;
        __stcs(drow, make_uint4(q[0], q[1], q[2], q[3]));
        __stcs(drow + 1, make_uint4(q[4], q[5], q[6], q[7]));
    }
}

extern "C" void kernel_launch(void* const* d_in, const int* in_sizes, int n_in,
                              void* d_out, int out_size) {
    const float4* emb_user = (const float4*)d_in[0];
    const float4* emb_item = (const float4*)d_in[1];
    const int* edge_row = (const int*)d_in[2];
    const int* edge_col = (const int*)d_in[3];
    const float* edge_val = (const float*)d_in[4];
    float4* out = (float4*)d_out;

    __half *X, *A, *B;
    int *count_, *offsetL_, *pos_, *bsum_, *rowOrder_;
    int2 *pair_;
    cudaGetSymbolAddress((void**)&X, g_bufX);
    cudaGetSymbolAddress((void**)&A, g_bufA);
    cudaGetSymbolAddress((void**)&B, g_bufB);
    cudaGetSymbolAddress((void**)&count_, g_count);
    cudaGetSymbolAddress((void**)&offsetL_, g_offsetL);
    cudaGetSymbolAddress((void**)&pos_, g_pos);
    cudaGetSymbolAddress((void**)&bsum_, g_bsum);
    cudaGetSymbolAddress((void**)&rowOrder_, g_rowOrder);
    cudaGetSymbolAddress((void**)&pair_, g_pair);

    const int T = 256;
    const int gridEdge4 = (N_EDGES / 4 + T - 1) / T;
    const int gridNode = (N_NODES + T - 1) / T;
    const int TS = 256;
    const int gridRow = (int)(((size_t)N_NODES * 8 + TS - 1) / TS);

    // ---- build ----
    hist_convert_kernel<<<gridEdge4 * 4, T>>>((const int4*)edge_row, count_,
                                              emb_user, emb_item, (uint2*)X);
    scan1_kernel<<<N_SCAN_BLOCKS, SCAN_BLOCK>>>(count_, offsetL_, pos_, bsum_);
    scan2_kernel<<<1, SCAN_BLOCK>>>(bsum_, N_SCAN_BLOCKS);
    rowsort_kernel<<<gridNode, T>>>(count_, rowOrder_);
    permute_kernel<<<gridEdge4, T>>>((const int4*)edge_row,
                                     (const int4*)edge_col,
                                     (const float4*)edge_val,
                                     pos_, bsum_, pair_);

    // ---- Layer 1: gather X -> A ----
    spmm_kernel<false><<<gridRow, TS>>>(offsetL_, bsum_, rowOrder_, pair_, X, A,
                                        nullptr, nullptr, nullptr, nullptr,
                                        nullptr);
    // ---- Layer 2: gather A -> B ----
    spmm_kernel<false><<<gridRow, TS>>>(offsetL_, bsum_, rowOrder_, pair_, A, B,
                                        nullptr, nullptr, nullptr, nullptr,
                                        nullptr);
    // ---- Layer 3 fused ----
    spmm_kernel<true><<<gridRow, TS>>>(offsetL_, bsum_, rowOrder_, pair_, B,
                                       nullptr, emb_user, emb_item, A, B, out);
}

// round 17
// speedup vs baseline: 1.2113x; 1.2113x over previous
#include <cuda_runtime.h>
#include <cuda_fp16.h>
#include <cstdint>

#define N_USERS 200000
#define N_ITEMS 400000
#define N_NODES 600000
#define EMB_DIM 128
#define N_EDGES 3000000
#define VEC4_PER_ROW 32
#define TOTAL_F ((size_t)N_NODES * EMB_DIM)
#define TOTAL_V4 (TOTAL_F / 4)

#define SCAN_BLOCK 1024
#define N_SCAN_BLOCKS ((N_NODES + SCAN_BLOCK - 1) / SCAN_BLOCK)  // 586

// Static scratch (allowed: __device__ globals; zero-init on load)
__device__ __align__(256) __half g_bufX[TOTAL_F];   // fp16 inputs, 153.6 MB
__device__ __align__(256) __half g_bufA[TOTAL_F];
__device__ __align__(256) __half g_bufB[TOTAL_F];
__device__ int  g_count[N_NODES];    // re-zeroed every replay by scan1
__device__ int  g_offsetL[N_NODES];
__device__ int  g_pos[N_NODES];
__device__ int  g_bsum[SCAN_BLOCK];
__device__ int2 g_pair[N_EDGES];     // (col, val-as-int), CSR order

// ---------------------------------------------------------------------------
// Launch 1: histogram (4 edges/thread) + fp32->fp16 conversion
// ---------------------------------------------------------------------------
__global__ void hist_convert_kernel(const int4* __restrict__ rows4,
                                    int* __restrict__ count,
                                    const float4* __restrict__ user,
                                    const float4* __restrict__ item,
                                    uint2* __restrict__ X2) {
    size_t tid = (size_t)blockIdx.x * blockDim.x + threadIdx.x;
    if (tid < N_EDGES / 4) {
        int4 r4 = __ldcs(rows4 + tid);
        atomicAdd(&count[r4.x], 1);
        atomicAdd(&count[r4.y], 1);
        atomicAdd(&count[r4.z], 1);
        atomicAdd(&count[r4.w], 1);
    }
    const size_t user_v4 = (size_t)N_USERS * VEC4_PER_ROW;
    size_t stride = (size_t)gridDim.x * blockDim.x;
    for (size_t i = tid; i < TOTAL_V4; i += stride) {
        float4 v = (i < user_v4) ? __ldcs(user + i) : __ldcs(item + i - user_v4);
        __half2 h0 = __floats2half2_rn(v.x, v.y);
        __half2 h1 = __floats2half2_rn(v.z, v.w);
        uint2 raw;
        raw.x = *reinterpret_cast<unsigned*>(&h0);
        raw.y = *reinterpret_cast<unsigned*>(&h1);
        __stcs(X2 + i, raw);
    }
}

// ---------------------------------------------------------------------------
// Launch 2: block-local exclusive scan; zeroes count; seeds pos
// ---------------------------------------------------------------------------
__global__ void scan1_kernel(int* __restrict__ count,
                             int* __restrict__ offsetL,
                             int* __restrict__ pos,
                             int* __restrict__ bsum) {
    __shared__ int sh[SCAN_BLOCK];
    int i = blockIdx.x * SCAN_BLOCK + threadIdx.x;
    int v = (i < N_NODES) ? count[i] : 0;
    if (i < N_NODES) count[i] = 0;   // restore replay invariant
    sh[threadIdx.x] = v;
    __syncthreads();
    #pragma unroll
    for (int d = 1; d < SCAN_BLOCK; d <<= 1) {
        int t = (threadIdx.x >= d) ? sh[threadIdx.x - d] : 0;
        __syncthreads();
        sh[threadIdx.x] += t;
        __syncthreads();
    }
    if (i < N_NODES) {
        int excl = sh[threadIdx.x] - v;
        offsetL[i] = excl;
        pos[i] = excl;
    }
    if (threadIdx.x == SCAN_BLOCK - 1) bsum[blockIdx.x] = sh[SCAN_BLOCK - 1];
}

// ---------------------------------------------------------------------------
// Launch 3: exclusive scan of block sums (single block)
// ---------------------------------------------------------------------------
__global__ void scan2_kernel(int* __restrict__ bsum, int nb) {
    __shared__ int sh[SCAN_BLOCK];
    int v = (threadIdx.x < nb) ? bsum[threadIdx.x] : 0;
    sh[threadIdx.x] = v;
    __syncthreads();
    #pragma unroll
    for (int d = 1; d < SCAN_BLOCK; d <<= 1) {
        int t = (threadIdx.x >= d) ? sh[threadIdx.x - d] : 0;
        __syncthreads();
        sh[threadIdx.x] += t;
        __syncthreads();
    }
    if (threadIdx.x < nb) bsum[threadIdx.x] = sh[threadIdx.x] - v;  // exclusive
}

// ---------------------------------------------------------------------------
// Launch 4: permute (4 edges/thread)
// ---------------------------------------------------------------------------
__global__ void permute_kernel(const int4* __restrict__ rows4,
                               const int4* __restrict__ cols4,
                               const float4* __restrict__ vals4,
                               int* __restrict__ pos,
                               const int* __restrict__ bsum,
                               int2* __restrict__ pair) {
    int t = blockIdx.x * blockDim.x + threadIdx.x;
    if (t >= N_EDGES / 4) return;
    int4 r4 = __ldcs(rows4 + t);
    int4 c4 = __ldcs(cols4 + t);
    float4 v4 = __ldcs(vals4 + t);

    int p0 = atomicAdd(&pos[r4.x], 1) + __ldg(&bsum[r4.x >> 10]);
    int p1 = atomicAdd(&pos[r4.y], 1) + __ldg(&bsum[r4.y >> 10]);
    int p2 = atomicAdd(&pos[r4.z], 1) + __ldg(&bsum[r4.z >> 10]);
    int p3 = atomicAdd(&pos[r4.w], 1) + __ldg(&bsum[r4.w >> 10]);

    int2 e;
    e.x = c4.x; e.y = __float_as_int(v4.x); __stcs(pair + p0, e);
    e.x = c4.y; e.y = __float_as_int(v4.y); __stcs(pair + p1, e);
    e.x = c4.z; e.y = __float_as_int(v4.z); __stcs(pair + p2, e);
    e.x = c4.w; e.y = __float_as_int(v4.w); __stcs(pair + p3, e);
}

// ---------------------------------------------------------------------------
// Gather (exact R9 form): LDG.256 + L2 evict_last, FMA into 16 fp32 accs
// ---------------------------------------------------------------------------
__device__ __forceinline__ void gather_acc(const __half* __restrict__ srcH,
                                           int col, int sub, float v,
                                           float* acc) {
    const char* p = reinterpret_cast<const char*>(srcH)
                    + ((size_t)col << 8) + (sub << 5);
    uint32_t q0, q1, q2, q3, q4, q5, q6, q7;
    asm volatile(
        "ld.global.nc.L2::evict_last.v8.b32 {%0,%1,%2,%3,%4,%5,%6,%7}, [%8];"
        : "=r"(q0), "=r"(q1), "=r"(q2), "=r"(q3),
          "=r"(q4), "=r"(q5), "=r"(q6), "=r"(q7)
        : "l"(p));
    uint32_t q[8] = {q0, q1, q2, q3, q4, q5, q6, q7};
    #pragma unroll
    for (int i = 0; i < 8; ++i) {
        __half2 h = *reinterpret_cast<__half2*>(&q[i]);
        float2 f = __half22float2(h);
        acc[2 * i]     += v * f.x;
        acc[2 * i + 1] += v * f.y;
    }
}

__device__ __forceinline__ void unpack16(uint4 lo, uint4 hi, float* f) {
    uint32_t q[8] = {lo.x, lo.y, lo.z, lo.w, hi.x, hi.y, hi.z, hi.w};
    #pragma unroll
    for (int i = 0; i < 8; ++i) {
        __half2 h = *reinterpret_cast<__half2*>(&q[i]);
        float2 t = __half22float2(h);
        f[2 * i] = t.x;
        f[2 * i + 1] = t.y;
    }
}

// ---------------------------------------------------------------------------
// Launches 5-7: pull SpMM — exact R9 body. 8-lane group per row, lane owns
// 16 elems (32B fp16), x2 unroll + remainder, evict_last gathers.
// FUSED (layer 3): out = 0.25*(x0 + A + B + y); x0 read from fp16 X buffer
// (streaming, 154 MB instead of 307 MB fp32 inputs).
// ---------------------------------------------------------------------------
template <bool FUSED>
__global__ void __launch_bounds__(256)
spmm_kernel(const int* __restrict__ offsetL,
            const int* __restrict__ bsum,
            const int2* __restrict__ pair,
            const __half* __restrict__ xH,    // gather src (fp16, L2-pinned)
            __half* __restrict__ dstH,        // layer output (fp16)
            const __half* __restrict__ x0H,   // FUSED: fp16 concat inputs (X)
            const __half* __restrict__ accA,  // FUSED: layer-1 out
            const __half* __restrict__ accB,  // FUSED: layer-2 out
            float4* __restrict__ out) {       // FUSED: final out fp32
    int sub = threadIdx.x & 7;
    int r = (blockIdx.x * blockDim.x + threadIdx.x) >> 3;
    if (r >= N_NODES) return;

    int j = __ldg(offsetL + r) + __ldg(bsum + (r >> 10));
    int end = (r == N_NODES - 1)
                  ? N_EDGES
                  : __ldg(offsetL + r + 1) + __ldg(bsum + ((r + 1) >> 10));

    float acc[16];
    #pragma unroll
    for (int k = 0; k < 16; ++k) acc[k] = 0.f;

    #pragma unroll 1
    for (; j + 2 <= end; j += 2) {
        int2 e0 = __ldcs(pair + j);        // 8 lanes same addr: broadcast
        int2 e1 = __ldcs(pair + j + 1);
        gather_acc(xH, e0.x, sub, __int_as_float(e0.y), acc);
        gather_acc(xH, e1.x, sub, __int_as_float(e1.y), acc);
    }
    if (j < end) {
        int2 e0 = __ldcs(pair + j);
        gather_acc(xH, e0.x, sub, __int_as_float(e0.y), acc);
    }

    if (FUSED) {
        const uint4* xRow = reinterpret_cast<const uint4*>(x0H + (size_t)r * EMB_DIM);
        const uint4* aRow = reinterpret_cast<const uint4*>(accA + (size_t)r * EMB_DIM);
        const uint4* bRow = reinterpret_cast<const uint4*>(accB + (size_t)r * EMB_DIM);
        float x0[16], a[16], b[16];
        unpack16(__ldcs(xRow + 2 * sub), __ldcs(xRow + 2 * sub + 1), x0);
        unpack16(__ldcs(aRow + 2 * sub), __ldcs(aRow + 2 * sub + 1), a);
        unpack16(__ldcs(bRow + 2 * sub), __ldcs(bRow + 2 * sub + 1), b);

        float4* orow = out + (size_t)r * VEC4_PER_ROW + 4 * sub;
        #pragma unroll
        for (int q = 0; q < 4; ++q) {
            float4 o;
            o.x = 0.25f * (x0[4 * q + 0] + a[4 * q + 0] + b[4 * q + 0] + acc[4 * q + 0]);
            o.y = 0.25f * (x0[4 * q + 1] + a[4 * q + 1] + b[4 * q + 1] + acc[4 * q + 1]);
            o.z = 0.25f * (x0[4 * q + 2] + a[4 * q + 2] + b[4 * q + 2] + acc[4 * q + 2]);
            o.w = 0.25f * (x0[4 * q + 3] + a[4 * q + 3] + b[4 * q + 3] + acc[4 * q + 3]);
            __stcs(orow + q, o);
        }
    } else {
        uint32_t q[8];
        #pragma unroll
        for (int i = 0; i < 8; ++i) {
            __half2 h = __floats2half2_rn(acc[2 * i], acc[2 * i + 1]);
            q[i] = *reinterpret_cast<unsigned*>(&h);
        }
        uint4* drow = reinterpret_cast<uint4*>(dstH + (size_t)r * EMB_DIM) + 2 * sub;
        __stcs(drow, make_uint4(q[0], q[1], q[2], q[3]));
        __stcs(drow + 1, make_uint4(q[4], q[5], q[6], q[7]));
    }
}

extern "C" void kernel_launch(void* const* d_in, const int* in_sizes, int n_in,
                              void* d_out, int out_size) {
    const float4* emb_user = (const float4*)d_in[0];
    const float4* emb_item = (const float4*)d_in[1];
    const int* edge_row = (const int*)d_in[2];
    const int* edge_col = (const int*)d_in[3];
    const float* edge_val = (const float*)d_in[4];
    float4* out = (float4*)d_out;

    __half *X, *A, *B;
    int *count_, *offsetL_, *pos_, *bsum_;
    int2 *pair_;
    cudaGetSymbolAddress((void**)&X, g_bufX);
    cudaGetSymbolAddress((void**)&A, g_bufA);
    cudaGetSymbolAddress((void**)&B, g_bufB);
    cudaGetSymbolAddress((void**)&count_, g_count);
    cudaGetSymbolAddress((void**)&offsetL_, g_offsetL);
    cudaGetSymbolAddress((void**)&pos_, g_pos);
    cudaGetSymbolAddress((void**)&bsum_, g_bsum);
    cudaGetSymbolAddress((void**)&pair_, g_pair);

    const int T = 256;
    const int gridEdge4 = (N_EDGES / 4 + T - 1) / T;
    const int TS = 256;
    const int gridRow = (int)(((size_t)N_NODES * 8 + TS - 1) / TS);

    // ---- build ----
    hist_convert_kernel<<<gridEdge4 * 4, T>>>((const int4*)edge_row, count_,
                                              emb_user, emb_item, (uint2*)X);
    scan1_kernel<<<N_SCAN_BLOCKS, SCAN_BLOCK>>>(count_, offsetL_, pos_, bsum_);
    scan2_kernel<<<1, SCAN_BLOCK>>>(bsum_, N_SCAN_BLOCKS);
    permute_kernel<<<gridEdge4, T>>>((const int4*)edge_row,
                                     (const int4*)edge_col,
                                     (const float4*)edge_val,
                                     pos_, bsum_, pair_);

    // ---- Layer 1: gather X -> A ----
    spmm_kernel<false><<<gridRow, TS>>>(offsetL_, bsum_, pair_, X, A,
                                        nullptr, nullptr, nullptr, nullptr);
    // ---- Layer 2: gather A -> B ----
    spmm_kernel<false><<<gridRow, TS>>>(offsetL_, bsum_, pair_, A, B,
                                        nullptr, nullptr, nullptr, nullptr);
    // ---- Layer 3 fused: gather B, out = 0.25*(X + A + B + y) ----
    spmm_kernel<true><<<gridRow, TS>>>(offsetL_, bsum_, pair_, B, nullptr,
                                       X, A, B, out);
}